// round 7
// baseline (speedup 1.0000x reference)
// R7: register double-buffered fragments (overlap LDSM with HMMA), merged pre-pass.
// BM=128 BN=128 BK=64, 128 thr, 3-stage cp.async, 144B pitch, 2 CTAs/SM.
#include <cuda_runtime.h>
#include <cuda_fp16.h>
#include <cstdint>

static constexpr int IN_F  = 4096;
static constexpr int OUT_F = 11008;
static constexpr int M_TOTAL = 8192;

static constexpr int BM = 128;
static constexpr int BN = 128;
static constexpr int BK = 64;
static constexpr int STAGES = 3;
static constexpr int NIT = IN_F / BK;           // 64

static constexpr int ROW_PITCH = 144;           // 128B data + 16B pad
static constexpr int A_STAGE = BM * ROW_PITCH;
static constexpr int B_STAGE = BN * ROW_PITCH;
static constexpr int STAGE_BYTES = A_STAGE + B_STAGE;     // 36864
static constexpr int SMEM_TOTAL = STAGES * STAGE_BYTES;   // 110592

static constexpr int GRID_M = M_TOTAL / BM;     // 64
static constexpr int GRID_N = OUT_F / BN;       // 86

__device__ __align__(128) __half g_wf16[(size_t)OUT_F * IN_F];    // 90 MB
__device__ __align__(128) __half g_xf16[(size_t)M_TOTAL * IN_F];  // 64 MB

// ---------------- helpers ----------------
__device__ __forceinline__ uint32_t smem_to_u32(const void* p) {
    uint32_t a;
    asm("{ .reg .u64 t; cvta.to.shared.u64 t, %1; cvt.u32.u64 %0, t; }" : "=r"(a) : "l"(p));
    return a;
}
#define CP_ASYNC16(saddr, gptr) \
    asm volatile("cp.async.cg.shared.global [%0], [%1], 16;" :: "r"((uint32_t)(saddr)), "l"(gptr) : "memory")
#define CP_COMMIT() asm volatile("cp.async.commit_group;" ::: "memory")
#define CP_WAIT1()  asm volatile("cp.async.wait_group 1;"  ::: "memory")

#define LDSM_X4(r0, r1, r2, r3, addr) \
    asm volatile("ldmatrix.sync.aligned.m8n8.x4.shared.b16 {%0,%1,%2,%3}, [%4];" \
        : "=r"(r0), "=r"(r1), "=r"(r2), "=r"(r3) : "r"(addr))

#define MMA16816(d0, d1, d2, d3, a0, a1, a2, a3, b0, b1) \
    asm volatile("mma.sync.aligned.m16n8k16.row.col.f32.f16.f16.f32 " \
        "{%0,%1,%2,%3}, {%4,%5,%6,%7}, {%8,%9}, {%0,%1,%2,%3};" \
        : "+f"(d0), "+f"(d1), "+f"(d2), "+f"(d3) \
        : "r"(a0), "r"(a1), "r"(a2), "r"(a3), "r"(b0), "r"(b1))

// ---------------- merged pre-pass: W i32->fp16 then x f32->fp16 ----------------
static constexpr size_t WTOT = (size_t)OUT_F * IN_F;   // 45,088,768
static constexpr size_t XTOT = (size_t)M_TOTAL * IN_F; // 33,554,432

__global__ void __launch_bounds__(256) convert_all_kernel(
    const int* __restrict__ qw, const float* __restrict__ x)
{
    size_t i = ((size_t)blockIdx.x * blockDim.x + threadIdx.x) * 8;
    if (i < WTOT) {
        const int4 v0 = *reinterpret_cast<const int4*>(qw + i);
        const int4 v1 = *reinterpret_cast<const int4*>(qw + i + 4);
        __half h[8];
        h[0] = __int2half_rn(v0.x); h[1] = __int2half_rn(v0.y);
        h[2] = __int2half_rn(v0.z); h[3] = __int2half_rn(v0.w);
        h[4] = __int2half_rn(v1.x); h[5] = __int2half_rn(v1.y);
        h[6] = __int2half_rn(v1.z); h[7] = __int2half_rn(v1.w);
        *reinterpret_cast<uint4*>(g_wf16 + i) = *reinterpret_cast<const uint4*>(h);
    } else {
        const size_t j = i - WTOT;
        if (j >= XTOT) return;
        const float4 v0 = *reinterpret_cast<const float4*>(x + j);
        const float4 v1 = *reinterpret_cast<const float4*>(x + j + 4);
        __half h[8];
        h[0] = __float2half_rn(v0.x); h[1] = __float2half_rn(v0.y);
        h[2] = __float2half_rn(v0.z); h[3] = __float2half_rn(v0.w);
        h[4] = __float2half_rn(v1.x); h[5] = __float2half_rn(v1.y);
        h[6] = __float2half_rn(v1.z); h[7] = __float2half_rn(v1.w);
        *reinterpret_cast<uint4*>(g_xf16 + j) = *reinterpret_cast<const uint4*>(h);
    }
}

// ---------------- main GEMM ----------------
__global__ void __launch_bounds__(128, 2) w8_gemm_kernel(
    const float* __restrict__ scale,
    const float* __restrict__ bias,
    float* __restrict__ out)
{
    extern __shared__ __align__(16) char smem_raw[];
    const uint32_t smem = smem_to_u32(smem_raw);

    const int tid  = threadIdx.x;
    const int lane = tid & 31;
    const int wid  = tid >> 5;
    const int warp_m = wid & 1;
    const int warp_n = wid >> 1;

    const int m0 = blockIdx.x * BM;
    const int n0 = blockIdx.y * BN;

    // cp.async coords: 128 rows x 8 chunks; 8 chunks/thread per tile
    const int base_r = tid >> 3;
    const int ch     = tid & 7;
    const uint32_t sOff0 = (uint32_t)(base_r * ROW_PITCH + ch * 16);
    const __half* gA0 = g_xf16 + (size_t)(m0 + base_r) * IN_F + ch * 8;
    const __half* gB0 = g_wf16 + (size_t)(n0 + base_r) * IN_F + ch * 8;

    // ldmatrix lane addresses
    const uint32_t a_lm = (uint32_t)((warp_m * 64 + (lane & 15)) * ROW_PITCH + (lane >> 4) * 16);
    const uint32_t b_lm = (uint32_t)((warp_n * 64 + (lane & 7) + ((lane >> 4) << 3)) * ROW_PITCH
                                     + ((lane >> 3) & 1) * 16);

    float acc[4][8][4];
#pragma unroll
    for (int mi = 0; mi < 4; mi++)
#pragma unroll
        for (int ni = 0; ni < 8; ni++)
#pragma unroll
            for (int j = 0; j < 4; j++) acc[mi][ni][j] = 0.f;

    // prologue: stages 0,1
#pragma unroll
    for (int s = 0; s < STAGES - 1; s++) {
        const uint32_t as = smem + s * STAGE_BYTES;
        const uint32_t bs = as + A_STAGE;
        const int k0 = s * BK;
#pragma unroll
        for (int j = 0; j < 8; j++) {
            CP_ASYNC16(as + sOff0 + j * 16 * ROW_PITCH, gA0 + (size_t)j * 16 * IN_F + k0);
            CP_ASYNC16(bs + sOff0 + j * 16 * ROW_PITCH, gB0 + (size_t)j * 16 * IN_F + k0);
        }
        CP_COMMIT();
    }

    int cur = 0, nxt = STAGES - 1;
    for (int it = 0; it < NIT; ++it) {
        CP_WAIT1();
        __syncthreads();

        if (it + STAGES - 1 < NIT) {
            const uint32_t as = smem + nxt * STAGE_BYTES;
            const uint32_t bs = as + A_STAGE;
            const int k0 = (it + STAGES - 1) * BK;
#pragma unroll
            for (int j = 0; j < 8; j++) {
                CP_ASYNC16(as + sOff0 + j * 16 * ROW_PITCH, gA0 + (size_t)j * 16 * IN_F + k0);
                CP_ASYNC16(bs + sOff0 + j * 16 * ROW_PITCH, gB0 + (size_t)j * 16 * IN_F + k0);
            }
        }
        CP_COMMIT();

        const uint32_t as = smem + cur * STAGE_BYTES;
        const uint32_t bs = as + A_STAGE;

        // ---- register double-buffered fragment pipeline ----
        uint32_t a[2][4][4], b[2][4][4];
#pragma unroll
        for (int mi = 0; mi < 4; mi++)
            LDSM_X4(a[0][mi][0], a[0][mi][1], a[0][mi][2], a[0][mi][3],
                    as + a_lm + mi * 16 * ROW_PITCH);
#pragma unroll
        for (int nt = 0; nt < 4; nt++)
            LDSM_X4(b[0][nt][0], b[0][nt][1], b[0][nt][2], b[0][nt][3],
                    bs + b_lm + nt * 16 * ROW_PITCH);

#pragma unroll
        for (int ks = 0; ks < 4; ks++) {
            const int cb = ks & 1, nb = cb ^ 1;
            if (ks < 3) {
                // prefetch ks+1 fragments: independent of in-flight MMAs below
#pragma unroll
                for (int mi = 0; mi < 4; mi++)
                    LDSM_X4(a[nb][mi][0], a[nb][mi][1], a[nb][mi][2], a[nb][mi][3],
                            as + a_lm + mi * 16 * ROW_PITCH + (ks + 1) * 32);
#pragma unroll
                for (int nt = 0; nt < 4; nt++)
                    LDSM_X4(b[nb][nt][0], b[nb][nt][1], b[nb][nt][2], b[nb][nt][3],
                            bs + b_lm + nt * 16 * ROW_PITCH + (ks + 1) * 32);
            }
#pragma unroll
            for (int mi = 0; mi < 4; mi++)
#pragma unroll
                for (int ni = 0; ni < 8; ni++)
                    MMA16816(acc[mi][ni][0], acc[mi][ni][1], acc[mi][ni][2], acc[mi][ni][3],
                             a[cb][mi][0], a[cb][mi][1], a[cb][mi][2], a[cb][mi][3],
                             b[cb][ni >> 1][(ni & 1) * 2], b[cb][ni >> 1][(ni & 1) * 2 + 1]);
        }

        cur = (cur + 1 == STAGES) ? 0 : cur + 1;
        nxt = (nxt + 1 == STAGES) ? 0 : nxt + 1;
    }

    // epilogue: y = round_fp16(acc*scale + bias) as float32
    const int qr = lane >> 2;
    const int qc = (lane & 3) * 2;
#pragma unroll
    for (int mi = 0; mi < 4; mi++) {
#pragma unroll
        for (int half_m = 0; half_m < 2; half_m++) {
            const int m = m0 + warp_m * 64 + mi * 16 + half_m * 8 + qr;
            float* orow = out + (size_t)m * OUT_F;
#pragma unroll
            for (int ni = 0; ni < 8; ni++) {
                const int n = n0 + warp_n * 64 + ni * 8 + qc;
                const float2 s2 = *reinterpret_cast<const float2*>(scale + n);
                const float2 b2 = *reinterpret_cast<const float2*>(bias + n);
                float y0 = acc[mi][ni][half_m * 2 + 0] * s2.x + b2.x;
                float y1 = acc[mi][ni][half_m * 2 + 1] * s2.y + b2.y;
                y0 = __half2float(__float2half_rn(y0));
                y1 = __half2float(__float2half_rn(y1));
                *reinterpret_cast<float2*>(orow + n) = make_float2(y0, y1);
            }
        }
    }
}

// ---------------- launch ----------------
extern "C" void kernel_launch(void* const* d_in, const int* in_sizes, int n_in,
                              void* d_out, int out_size) {
    const float* x     = (const float*)d_in[0];
    const int*   qw    = (const int*)d_in[1];
    const float* scale = (const float*)d_in[2];
    const float* bias  = (const float*)d_in[3];
    float*       out   = (float*)d_out;

    const size_t tot8 = (WTOT + XTOT) / 8;
    convert_all_kernel<<<(int)((tot8 + 255) / 256), 256>>>(qw, x);

    cudaFuncSetAttribute(w8_gemm_kernel, cudaFuncAttributeMaxDynamicSharedMemorySize, SMEM_TOTAL);
    dim3 grid(GRID_M, GRID_N);
    w8_gemm_kernel<<<grid, 128, SMEM_TOTAL>>>(scale, bias, out);
}

// round 8
// speedup vs baseline: 1.1260x; 1.1260x over previous
// R8: occupancy push — 2 CTAs/SM x 256 thr (16 warps/SM, 4/SMSP), warp tile 32x64,
// BM=128 BN=128 BK=64, 3-stage cp.async, 144B pitch, single barrier/iter.
// (R7 reg double-buffering reverted.) Merged i32->fp16 / f32->fp16 pre-pass.
#include <cuda_runtime.h>
#include <cuda_fp16.h>
#include <cstdint>

static constexpr int IN_F  = 4096;
static constexpr int OUT_F = 11008;
static constexpr int M_TOTAL = 8192;

static constexpr int BM = 128;
static constexpr int BN = 128;
static constexpr int BK = 64;
static constexpr int STAGES = 3;
static constexpr int NIT = IN_F / BK;           // 64

static constexpr int ROW_PITCH = 144;           // 128B data + 16B pad (conflict-free)
static constexpr int A_STAGE = BM * ROW_PITCH;
static constexpr int B_STAGE = BN * ROW_PITCH;
static constexpr int STAGE_BYTES = A_STAGE + B_STAGE;     // 36864
static constexpr int SMEM_TOTAL = STAGES * STAGE_BYTES;   // 110592 (x2 CTA = 216KB)

static constexpr int GRID_M = M_TOTAL / BM;     // 64
static constexpr int GRID_N = OUT_F / BN;       // 86

__device__ __align__(128) __half g_wf16[(size_t)OUT_F * IN_F];    // 90 MB
__device__ __align__(128) __half g_xf16[(size_t)M_TOTAL * IN_F];  // 64 MB

// ---------------- helpers ----------------
__device__ __forceinline__ uint32_t smem_to_u32(const void* p) {
    uint32_t a;
    asm("{ .reg .u64 t; cvta.to.shared.u64 t, %1; cvt.u32.u64 %0, t; }" : "=r"(a) : "l"(p));
    return a;
}
#define CP_ASYNC16(saddr, gptr) \
    asm volatile("cp.async.cg.shared.global [%0], [%1], 16;" :: "r"((uint32_t)(saddr)), "l"(gptr) : "memory")
#define CP_COMMIT() asm volatile("cp.async.commit_group;" ::: "memory")
#define CP_WAIT1()  asm volatile("cp.async.wait_group 1;"  ::: "memory")

#define LDSM_X4(r0, r1, r2, r3, addr) \
    asm volatile("ldmatrix.sync.aligned.m8n8.x4.shared.b16 {%0,%1,%2,%3}, [%4];" \
        : "=r"(r0), "=r"(r1), "=r"(r2), "=r"(r3) : "r"(addr))

#define MMA16816(d0, d1, d2, d3, a0, a1, a2, a3, b0, b1) \
    asm volatile("mma.sync.aligned.m16n8k16.row.col.f32.f16.f16.f32 " \
        "{%0,%1,%2,%3}, {%4,%5,%6,%7}, {%8,%9}, {%0,%1,%2,%3};" \
        : "+f"(d0), "+f"(d1), "+f"(d2), "+f"(d3) \
        : "r"(a0), "r"(a1), "r"(a2), "r"(a3), "r"(b0), "r"(b1))

// ---------------- merged pre-pass ----------------
static constexpr size_t WTOT = (size_t)OUT_F * IN_F;
static constexpr size_t XTOT = (size_t)M_TOTAL * IN_F;

__global__ void __launch_bounds__(256) convert_all_kernel(
    const int* __restrict__ qw, const float* __restrict__ x)
{
    size_t i = ((size_t)blockIdx.x * blockDim.x + threadIdx.x) * 8;
    if (i < WTOT) {
        const int4 v0 = *reinterpret_cast<const int4*>(qw + i);
        const int4 v1 = *reinterpret_cast<const int4*>(qw + i + 4);
        __half h[8];
        h[0] = __int2half_rn(v0.x); h[1] = __int2half_rn(v0.y);
        h[2] = __int2half_rn(v0.z); h[3] = __int2half_rn(v0.w);
        h[4] = __int2half_rn(v1.x); h[5] = __int2half_rn(v1.y);
        h[6] = __int2half_rn(v1.z); h[7] = __int2half_rn(v1.w);
        *reinterpret_cast<uint4*>(g_wf16 + i) = *reinterpret_cast<const uint4*>(h);
    } else {
        const size_t j = i - WTOT;
        if (j >= XTOT) return;
        const float4 v0 = *reinterpret_cast<const float4*>(x + j);
        const float4 v1 = *reinterpret_cast<const float4*>(x + j + 4);
        __half h[8];
        h[0] = __float2half_rn(v0.x); h[1] = __float2half_rn(v0.y);
        h[2] = __float2half_rn(v0.z); h[3] = __float2half_rn(v0.w);
        h[4] = __float2half_rn(v1.x); h[5] = __float2half_rn(v1.y);
        h[6] = __float2half_rn(v1.z); h[7] = __float2half_rn(v1.w);
        *reinterpret_cast<uint4*>(g_xf16 + j) = *reinterpret_cast<const uint4*>(h);
    }
}

// ---------------- main GEMM ----------------
__global__ void __launch_bounds__(256, 2) w8_gemm_kernel(
    const float* __restrict__ scale,
    const float* __restrict__ bias,
    float* __restrict__ out)
{
    extern __shared__ __align__(16) char smem_raw[];
    const uint32_t smem = smem_to_u32(smem_raw);

    const int tid  = threadIdx.x;
    const int lane = tid & 31;
    const int wid  = tid >> 5;
    const int warp_m = wid & 3;         // 4 row groups of 32
    const int warp_n = wid >> 2;        // 2 col groups of 64

    const int m0 = blockIdx.x * BM;
    const int n0 = blockIdx.y * BN;

    // cp.async coords: tile = 128 rows x 8 chunks(16B) = 1024 chunks; 4/thread.
    // chunk j: row = (tid>>3) + 32*j, ch = tid&7.
    const int base_r = tid >> 3;
    const int ch     = tid & 7;
    const uint32_t sOff0 = (uint32_t)(base_r * ROW_PITCH + ch * 16);   // +j*32*ROW_PITCH
    const __half* gA0 = g_xf16 + (size_t)(m0 + base_r) * IN_F + ch * 8; // +j*32*IN_F
    const __half* gB0 = g_wf16 + (size_t)(n0 + base_r) * IN_F + ch * 8;

    // ldmatrix lane addresses
    // A: row = warp_m*32 + (lane&15), chunk = lane>>4 ; +mi*16 rows ; +ks*32B
    const uint32_t a_lm = (uint32_t)((warp_m * 32 + (lane & 15)) * ROW_PITCH + (lane >> 4) * 16);
    // B: row = warp_n*64 + (lane&7) + ((lane>>4)<<3), chunk = (lane>>3)&1 ; +nt*16 rows ; +ks*32B
    const uint32_t b_lm = (uint32_t)((warp_n * 64 + (lane & 7) + ((lane >> 4) << 3)) * ROW_PITCH
                                     + ((lane >> 3) & 1) * 16);

    float acc[2][8][4];
#pragma unroll
    for (int mi = 0; mi < 2; mi++)
#pragma unroll
        for (int ni = 0; ni < 8; ni++)
#pragma unroll
            for (int j = 0; j < 4; j++) acc[mi][ni][j] = 0.f;

    // prologue: stages 0,1
#pragma unroll
    for (int s = 0; s < STAGES - 1; s++) {
        const uint32_t as = smem + s * STAGE_BYTES;
        const uint32_t bs = as + A_STAGE;
        const int k0 = s * BK;
#pragma unroll
        for (int j = 0; j < 4; j++) {
            CP_ASYNC16(as + sOff0 + j * 32 * ROW_PITCH, gA0 + (size_t)j * 32 * IN_F + k0);
            CP_ASYNC16(bs + sOff0 + j * 32 * ROW_PITCH, gB0 + (size_t)j * 32 * IN_F + k0);
        }
        CP_COMMIT();
    }

    int cur = 0, nxt = STAGES - 1;
    for (int it = 0; it < NIT; ++it) {
        CP_WAIT1();
        __syncthreads();   // publishes stage cur; fences all warps past compute(it-1)

        if (it + STAGES - 1 < NIT) {
            const uint32_t as = smem + nxt * STAGE_BYTES;
            const uint32_t bs = as + A_STAGE;
            const int k0 = (it + STAGES - 1) * BK;
#pragma unroll
            for (int j = 0; j < 4; j++) {
                CP_ASYNC16(as + sOff0 + j * 32 * ROW_PITCH, gA0 + (size_t)j * 32 * IN_F + k0);
                CP_ASYNC16(bs + sOff0 + j * 32 * ROW_PITCH, gB0 + (size_t)j * 32 * IN_F + k0);
            }
        }
        CP_COMMIT();

        const uint32_t as = smem + cur * STAGE_BYTES;
        const uint32_t bs = as + A_STAGE;
#pragma unroll
        for (int ks = 0; ks < 4; ks++) {
            uint32_t a[2][4];
#pragma unroll
            for (int mi = 0; mi < 2; mi++)
                LDSM_X4(a[mi][0], a[mi][1], a[mi][2], a[mi][3],
                        as + a_lm + mi * 16 * ROW_PITCH + ks * 32);
            uint32_t b[4][4];
#pragma unroll
            for (int nt = 0; nt < 4; nt++)
                LDSM_X4(b[nt][0], b[nt][1], b[nt][2], b[nt][3],
                        bs + b_lm + nt * 16 * ROW_PITCH + ks * 32);
#pragma unroll
            for (int mi = 0; mi < 2; mi++)
#pragma unroll
                for (int ni = 0; ni < 8; ni++)
                    MMA16816(acc[mi][ni][0], acc[mi][ni][1], acc[mi][ni][2], acc[mi][ni][3],
                             a[mi][0], a[mi][1], a[mi][2], a[mi][3],
                             b[ni >> 1][(ni & 1) * 2], b[ni >> 1][(ni & 1) * 2 + 1]);
        }

        cur = (cur + 1 == STAGES) ? 0 : cur + 1;
        nxt = (nxt + 1 == STAGES) ? 0 : nxt + 1;
    }

    // epilogue: y = round_fp16(acc*scale + bias) as float32
    const int qr = lane >> 2;
    const int qc = (lane & 3) * 2;
#pragma unroll
    for (int mi = 0; mi < 2; mi++) {
#pragma unroll
        for (int half_m = 0; half_m < 2; half_m++) {
            const int m = m0 + warp_m * 32 + mi * 16 + half_m * 8 + qr;
            float* orow = out + (size_t)m * OUT_F;
#pragma unroll
            for (int ni = 0; ni < 8; ni++) {
                const int n = n0 + warp_n * 64 + ni * 8 + qc;
                const float2 s2 = *reinterpret_cast<const float2*>(scale + n);
                const float2 b2 = *reinterpret_cast<const float2*>(bias + n);
                float y0 = acc[mi][ni][half_m * 2 + 0] * s2.x + b2.x;
                float y1 = acc[mi][ni][half_m * 2 + 1] * s2.y + b2.y;
                y0 = __half2float(__float2half_rn(y0));
                y1 = __half2float(__float2half_rn(y1));
                *reinterpret_cast<float2*>(orow + n) = make_float2(y0, y1);
            }
        }
    }
}

// ---------------- launch ----------------
extern "C" void kernel_launch(void* const* d_in, const int* in_sizes, int n_in,
                              void* d_out, int out_size) {
    const float* x     = (const float*)d_in[0];
    const int*   qw    = (const int*)d_in[1];
    const float* scale = (const float*)d_in[2];
    const float* bias  = (const float*)d_in[3];
    float*       out   = (float*)d_out;

    const size_t tot8 = (WTOT + XTOT) / 8;
    convert_all_kernel<<<(int)((tot8 + 255) / 256), 256>>>(qw, x);

    cudaFuncSetAttribute(w8_gemm_kernel, cudaFuncAttributeMaxDynamicSharedMemorySize, SMEM_TOTAL);
    dim3 grid(GRID_M, GRID_N);
    w8_gemm_kernel<<<grid, 256, SMEM_TOTAL>>>(scale, bias, out);
}

// round 9
// speedup vs baseline: 1.2130x; 1.0772x over previous
// R9: mbarrier full/empty ring replaces per-iter __syncthreads (lockstep kill).
// BM=128 BN=128 BK=64, 256 thr (warp tile 32x64), 3 stages, 144B pitch, 2 CTAs/SM.
#include <cuda_runtime.h>
#include <cuda_fp16.h>
#include <cstdint>

static constexpr int IN_F  = 4096;
static constexpr int OUT_F = 11008;
static constexpr int M_TOTAL = 8192;

static constexpr int BM = 128;
static constexpr int BN = 128;
static constexpr int BK = 64;
static constexpr int STAGES = 3;
static constexpr int NIT = IN_F / BK;           // 64

static constexpr int ROW_PITCH = 144;           // 128B data + 16B pad (conflict-free)
static constexpr int A_STAGE = BM * ROW_PITCH;
static constexpr int B_STAGE = BN * ROW_PITCH;
static constexpr int STAGE_BYTES = A_STAGE + B_STAGE;               // 36864
static constexpr int SMEM_TOTAL = 128 + STAGES * STAGE_BYTES;       // 110720 (x2 CTA fits 228KB)

static constexpr int GRID_M = M_TOTAL / BM;     // 64
static constexpr int GRID_N = OUT_F / BN;       // 86

__device__ __align__(128) __half g_wf16[(size_t)OUT_F * IN_F];    // 90 MB
__device__ __align__(128) __half g_xf16[(size_t)M_TOTAL * IN_F];  // 64 MB

// ---------------- helpers ----------------
__device__ __forceinline__ uint32_t smem_to_u32(const void* p) {
    uint32_t a;
    asm("{ .reg .u64 t; cvta.to.shared.u64 t, %1; cvt.u32.u64 %0, t; }" : "=r"(a) : "l"(p));
    return a;
}
#define CP_ASYNC16(saddr, gptr) \
    asm volatile("cp.async.cg.shared.global [%0], [%1], 16;" :: "r"((uint32_t)(saddr)), "l"(gptr) : "memory")
#define CP_ASYNC_ARRIVE_NOINC(mbar) \
    asm volatile("cp.async.mbarrier.arrive.noinc.shared::cta.b64 [%0];" :: "r"((uint32_t)(mbar)) : "memory")
#define MBARRIER_INIT(addr, cnt) \
    asm volatile("mbarrier.init.shared.b64 [%0], %1;" :: "r"((uint32_t)(addr)), "r"((uint32_t)(cnt)) : "memory")
#define MBARRIER_ARRIVE(addr) \
    asm volatile("mbarrier.arrive.shared.b64 _, [%0];" :: "r"((uint32_t)(addr)) : "memory")

#define MBARRIER_WAIT_PARITY(mbar_smem_addr, phase_parity) do { \
    uint32_t _mbar = (uint32_t)(mbar_smem_addr); \
    uint32_t _parity = (uint32_t)(phase_parity); \
    uint32_t _done; \
    asm volatile( \
        "{\n\t.reg .pred p;\n\t" \
        "mbarrier.try_wait.parity.acquire.cta.shared::cta.b64 p, [%1], %2;\n\t" \
        "selp.b32 %0, 1, 0, p;\n\t}" \
        : "=r"(_done) : "r"(_mbar), "r"(_parity) : "memory"); \
    if (!_done) { \
        asm volatile( \
            "{\n\t.reg .pred P1;\n\t" \
            "WAIT_LOOP_%=:\n\t" \
            "mbarrier.try_wait.parity.acquire.cta.shared::cta.b64 P1, [%0], %1, 0x989680;\n\t" \
            "@P1 bra.uni WAIT_DONE_%=;\n\t" \
            "bra.uni WAIT_LOOP_%=;\n\t" \
            "WAIT_DONE_%=:\n\t}" \
            :: "r"(_mbar), "r"(_parity) : "memory"); \
    } \
} while(0)

#define LDSM_X4(r0, r1, r2, r3, addr) \
    asm volatile("ldmatrix.sync.aligned.m8n8.x4.shared.b16 {%0,%1,%2,%3}, [%4];" \
        : "=r"(r0), "=r"(r1), "=r"(r2), "=r"(r3) : "r"(addr))

#define MMA16816(d0, d1, d2, d3, a0, a1, a2, a3, b0, b1) \
    asm volatile("mma.sync.aligned.m16n8k16.row.col.f32.f16.f16.f32 " \
        "{%0,%1,%2,%3}, {%4,%5,%6,%7}, {%8,%9}, {%0,%1,%2,%3};" \
        : "+f"(d0), "+f"(d1), "+f"(d2), "+f"(d3) \
        : "r"(a0), "r"(a1), "r"(a2), "r"(a3), "r"(b0), "r"(b1))

// ---------------- merged pre-pass ----------------
static constexpr size_t WTOT = (size_t)OUT_F * IN_F;
static constexpr size_t XTOT = (size_t)M_TOTAL * IN_F;

__global__ void __launch_bounds__(256) convert_all_kernel(
    const int* __restrict__ qw, const float* __restrict__ x)
{
    size_t i = ((size_t)blockIdx.x * blockDim.x + threadIdx.x) * 8;
    if (i < WTOT) {
        const int4 v0 = *reinterpret_cast<const int4*>(qw + i);
        const int4 v1 = *reinterpret_cast<const int4*>(qw + i + 4);
        __half h[8];
        h[0] = __int2half_rn(v0.x); h[1] = __int2half_rn(v0.y);
        h[2] = __int2half_rn(v0.z); h[3] = __int2half_rn(v0.w);
        h[4] = __int2half_rn(v1.x); h[5] = __int2half_rn(v1.y);
        h[6] = __int2half_rn(v1.z); h[7] = __int2half_rn(v1.w);
        *reinterpret_cast<uint4*>(g_wf16 + i) = *reinterpret_cast<const uint4*>(h);
    } else {
        const size_t j = i - WTOT;
        if (j >= XTOT) return;
        const float4 v0 = *reinterpret_cast<const float4*>(x + j);
        const float4 v1 = *reinterpret_cast<const float4*>(x + j + 4);
        __half h[8];
        h[0] = __float2half_rn(v0.x); h[1] = __float2half_rn(v0.y);
        h[2] = __float2half_rn(v0.z); h[3] = __float2half_rn(v0.w);
        h[4] = __float2half_rn(v1.x); h[5] = __float2half_rn(v1.y);
        h[6] = __float2half_rn(v1.z); h[7] = __float2half_rn(v1.w);
        *reinterpret_cast<uint4*>(g_xf16 + j) = *reinterpret_cast<const uint4*>(h);
    }
}

// ---------------- main GEMM ----------------
__global__ void __launch_bounds__(256, 2) w8_gemm_kernel(
    const float* __restrict__ scale,
    const float* __restrict__ bias,
    float* __restrict__ out)
{
    extern __shared__ __align__(128) char smem_raw[];
    const uint32_t base  = smem_to_u32(smem_raw);
    const uint32_t tiles = base + 128;
    // barriers: full[s] = base + 8*s ; empty[s] = base + 24 + 8*s

    const int tid  = threadIdx.x;
    const int lane = tid & 31;
    const int wid  = tid >> 5;
    const int warp_m = wid & 3;         // 4 row groups of 32
    const int warp_n = wid >> 2;        // 2 col groups of 64

    const int m0 = blockIdx.x * BM;
    const int n0 = blockIdx.y * BN;

    if (tid == 0) {
#pragma unroll
        for (int s = 0; s < STAGES; s++) {
            MBARRIER_INIT(base + 8 * s, 256);       // full: all threads cp.async-arrive
            MBARRIER_INIT(base + 24 + 8 * s, 8);    // empty: one arrive per warp
        }
    }
    __syncthreads();

    // cp.async coords: tile = 128 rows x 8 chunks(16B); 4 A + 4 B chunks per thread.
    const int base_r = tid >> 3;
    const int ch     = tid & 7;
    const uint32_t sOff0 = (uint32_t)(base_r * ROW_PITCH + ch * 16);
    const __half* gA0 = g_xf16 + (size_t)(m0 + base_r) * IN_F + ch * 8;
    const __half* gB0 = g_wf16 + (size_t)(n0 + base_r) * IN_F + ch * 8;

    // ldmatrix lane addresses
    const uint32_t a_lm = (uint32_t)((warp_m * 32 + (lane & 15)) * ROW_PITCH + (lane >> 4) * 16);
    const uint32_t b_lm = (uint32_t)((warp_n * 64 + (lane & 7) + ((lane >> 4) << 3)) * ROW_PITCH
                                     + ((lane >> 3) & 1) * 16);

    float acc[2][8][4];
#pragma unroll
    for (int mi = 0; mi < 2; mi++)
#pragma unroll
        for (int ni = 0; ni < 8; ni++)
#pragma unroll
            for (int j = 0; j < 4; j++) acc[mi][ni][j] = 0.f;

    // ---- prologue: produce stages 0,1 (empty-waits pass at phase 1) ----
#pragma unroll
    for (int s = 0; s < STAGES - 1; s++) {
        MBARRIER_WAIT_PARITY(base + 24 + 8 * s, 1);
        const uint32_t as = tiles + s * STAGE_BYTES;
        const uint32_t bs = as + A_STAGE;
        const int k0 = s * BK;
#pragma unroll
        for (int j = 0; j < 4; j++) {
            CP_ASYNC16(as + sOff0 + j * 32 * ROW_PITCH, gA0 + (size_t)j * 32 * IN_F + k0);
            CP_ASYNC16(bs + sOff0 + j * 32 * ROW_PITCH, gB0 + (size_t)j * 32 * IN_F + k0);
        }
        CP_ASYNC_ARRIVE_NOINC(base + 8 * s);
    }

    int pstage = STAGES - 1, pphase = 1;   // producer cursor (prologue produced 0,1 @ phase 1)
    int cstage = 0,          cphase = 0;   // consumer cursor

    for (int it = 0; it < NIT; ++it) {
        // ---- produce stage for iteration it+2 ----
        if (it + STAGES - 1 < NIT) {
            MBARRIER_WAIT_PARITY(base + 24 + 8 * pstage, pphase);
            const uint32_t as = tiles + pstage * STAGE_BYTES;
            const uint32_t bs = as + A_STAGE;
            const int k0 = (it + STAGES - 1) * BK;
#pragma unroll
            for (int j = 0; j < 4; j++) {
                CP_ASYNC16(as + sOff0 + j * 32 * ROW_PITCH, gA0 + (size_t)j * 32 * IN_F + k0);
                CP_ASYNC16(bs + sOff0 + j * 32 * ROW_PITCH, gB0 + (size_t)j * 32 * IN_F + k0);
            }
            CP_ASYNC_ARRIVE_NOINC(base + 8 * pstage);
            if (++pstage == STAGES) { pstage = 0; pphase ^= 1; }
        }

        // ---- consume stage cstage ----
        MBARRIER_WAIT_PARITY(base + 8 * cstage, cphase);
        const uint32_t as = tiles + cstage * STAGE_BYTES;
        const uint32_t bs = as + A_STAGE;
#pragma unroll
        for (int ks = 0; ks < 4; ks++) {
            uint32_t a[2][4];
#pragma unroll
            for (int mi = 0; mi < 2; mi++)
                LDSM_X4(a[mi][0], a[mi][1], a[mi][2], a[mi][3],
                        as + a_lm + mi * 16 * ROW_PITCH + ks * 32);
            uint32_t b[4][4];
#pragma unroll
            for (int nt = 0; nt < 4; nt++)
                LDSM_X4(b[nt][0], b[nt][1], b[nt][2], b[nt][3],
                        bs + b_lm + nt * 16 * ROW_PITCH + ks * 32);
#pragma unroll
            for (int mi = 0; mi < 2; mi++)
#pragma unroll
                for (int ni = 0; ni < 8; ni++)
                    MMA16816(acc[mi][ni][0], acc[mi][ni][1], acc[mi][ni][2], acc[mi][ni][3],
                             a[mi][0], a[mi][1], a[mi][2], a[mi][3],
                             b[ni >> 1][(ni & 1) * 2], b[ni >> 1][(ni & 1) * 2 + 1]);
        }
        // final MMAs consumed the LDSM regs -> all this warp's smem reads complete
        if (lane == 0) MBARRIER_ARRIVE(base + 24 + 8 * cstage);
        if (++cstage == STAGES) { cstage = 0; cphase ^= 1; }
    }

    // ---- epilogue: y = round_fp16(acc*scale + bias) as float32 ----
    const int qr = lane >> 2;
    const int qc = (lane & 3) * 2;
#pragma unroll
    for (int mi = 0; mi < 2; mi++) {
#pragma unroll
        for (int half_m = 0; half_m < 2; half_m++) {
            const int m = m0 + warp_m * 32 + mi * 16 + half_m * 8 + qr;
            float* orow = out + (size_t)m * OUT_F;
#pragma unroll
            for (int ni = 0; ni < 8; ni++) {
                const int n = n0 + warp_n * 64 + ni * 8 + qc;
                const float2 s2 = *reinterpret_cast<const float2*>(scale + n);
                const float2 b2 = *reinterpret_cast<const float2*>(bias + n);
                float y0 = acc[mi][ni][half_m * 2 + 0] * s2.x + b2.x;
                float y1 = acc[mi][ni][half_m * 2 + 1] * s2.y + b2.y;
                y0 = __half2float(__float2half_rn(y0));
                y1 = __half2float(__float2half_rn(y1));
                *reinterpret_cast<float2*>(orow + n) = make_float2(y0, y1);
            }
        }
    }
}

// ---------------- launch ----------------
extern "C" void kernel_launch(void* const* d_in, const int* in_sizes, int n_in,
                              void* d_out, int out_size) {
    const float* x     = (const float*)d_in[0];
    const int*   qw    = (const int*)d_in[1];
    const float* scale = (const float*)d_in[2];
    const float* bias  = (const float*)d_in[3];
    float*       out   = (float*)d_out;

    const size_t tot8 = (WTOT + XTOT) / 8;
    convert_all_kernel<<<(int)((tot8 + 255) / 256), 256>>>(qw, x);

    cudaFuncSetAttribute(w8_gemm_kernel, cudaFuncAttributeMaxDynamicSharedMemorySize, SMEM_TOTAL);
    dim3 grid(GRID_M, GRID_N);
    w8_gemm_kernel<<<grid, 256, SMEM_TOTAL>>>(scale, bias, out);
}

// round 10
// speedup vs baseline: 1.3859x; 1.1426x over previous
// R10: consume-then-produce loop reorder (kill producer head-of-line blocking).
// Otherwise identical to R9: BM=128 BN=128 BK=64, 256 thr (warp 32x64), 3-stage
// mbarrier ring, 144B pitch, 2 CTAs/SM. Merged fp16-convert pre-pass.
#include <cuda_runtime.h>
#include <cuda_fp16.h>
#include <cstdint>

static constexpr int IN_F  = 4096;
static constexpr int OUT_F = 11008;
static constexpr int M_TOTAL = 8192;

static constexpr int BM = 128;
static constexpr int BN = 128;
static constexpr int BK = 64;
static constexpr int STAGES = 3;
static constexpr int NIT = IN_F / BK;           // 64

static constexpr int ROW_PITCH = 144;           // 128B data + 16B pad (conflict-free)
static constexpr int A_STAGE = BM * ROW_PITCH;
static constexpr int B_STAGE = BN * ROW_PITCH;
static constexpr int STAGE_BYTES = A_STAGE + B_STAGE;               // 36864
static constexpr int SMEM_TOTAL = 128 + STAGES * STAGE_BYTES;       // 110720

static constexpr int GRID_M = M_TOTAL / BM;     // 64
static constexpr int GRID_N = OUT_F / BN;       // 86

__device__ __align__(128) __half g_wf16[(size_t)OUT_F * IN_F];    // 90 MB
__device__ __align__(128) __half g_xf16[(size_t)M_TOTAL * IN_F];  // 64 MB

// ---------------- helpers ----------------
__device__ __forceinline__ uint32_t smem_to_u32(const void* p) {
    uint32_t a;
    asm("{ .reg .u64 t; cvta.to.shared.u64 t, %1; cvt.u32.u64 %0, t; }" : "=r"(a) : "l"(p));
    return a;
}
#define CP_ASYNC16(saddr, gptr) \
    asm volatile("cp.async.cg.shared.global [%0], [%1], 16;" :: "r"((uint32_t)(saddr)), "l"(gptr) : "memory")
#define CP_ASYNC_ARRIVE_NOINC(mbar) \
    asm volatile("cp.async.mbarrier.arrive.noinc.shared::cta.b64 [%0];" :: "r"((uint32_t)(mbar)) : "memory")
#define MBARRIER_INIT(addr, cnt) \
    asm volatile("mbarrier.init.shared.b64 [%0], %1;" :: "r"((uint32_t)(addr)), "r"((uint32_t)(cnt)) : "memory")
#define MBARRIER_ARRIVE(addr) \
    asm volatile("mbarrier.arrive.shared.b64 _, [%0];" :: "r"((uint32_t)(addr)) : "memory")

#define MBARRIER_WAIT_PARITY(mbar_smem_addr, phase_parity) do { \
    uint32_t _mbar = (uint32_t)(mbar_smem_addr); \
    uint32_t _parity = (uint32_t)(phase_parity); \
    uint32_t _done; \
    asm volatile( \
        "{\n\t.reg .pred p;\n\t" \
        "mbarrier.try_wait.parity.acquire.cta.shared::cta.b64 p, [%1], %2;\n\t" \
        "selp.b32 %0, 1, 0, p;\n\t}" \
        : "=r"(_done) : "r"(_mbar), "r"(_parity) : "memory"); \
    if (!_done) { \
        asm volatile( \
            "{\n\t.reg .pred P1;\n\t" \
            "WAIT_LOOP_%=:\n\t" \
            "mbarrier.try_wait.parity.acquire.cta.shared::cta.b64 P1, [%0], %1, 0x989680;\n\t" \
            "@P1 bra.uni WAIT_DONE_%=;\n\t" \
            "bra.uni WAIT_LOOP_%=;\n\t" \
            "WAIT_DONE_%=:\n\t}" \
            :: "r"(_mbar), "r"(_parity) : "memory"); \
    } \
} while(0)

#define LDSM_X4(r0, r1, r2, r3, addr) \
    asm volatile("ldmatrix.sync.aligned.m8n8.x4.shared.b16 {%0,%1,%2,%3}, [%4];" \
        : "=r"(r0), "=r"(r1), "=r"(r2), "=r"(r3) : "r"(addr))

#define MMA16816(d0, d1, d2, d3, a0, a1, a2, a3, b0, b1) \
    asm volatile("mma.sync.aligned.m16n8k16.row.col.f32.f16.f16.f32 " \
        "{%0,%1,%2,%3}, {%4,%5,%6,%7}, {%8,%9}, {%0,%1,%2,%3};" \
        : "+f"(d0), "+f"(d1), "+f"(d2), "+f"(d3) \
        : "r"(a0), "r"(a1), "r"(a2), "r"(a3), "r"(b0), "r"(b1))

// ---------------- merged pre-pass ----------------
static constexpr size_t WTOT = (size_t)OUT_F * IN_F;
static constexpr size_t XTOT = (size_t)M_TOTAL * IN_F;

__global__ void __launch_bounds__(256) convert_all_kernel(
    const int* __restrict__ qw, const float* __restrict__ x)
{
    size_t i = ((size_t)blockIdx.x * blockDim.x + threadIdx.x) * 8;
    if (i < WTOT) {
        const int4 v0 = *reinterpret_cast<const int4*>(qw + i);
        const int4 v1 = *reinterpret_cast<const int4*>(qw + i + 4);
        __half h[8];
        h[0] = __int2half_rn(v0.x); h[1] = __int2half_rn(v0.y);
        h[2] = __int2half_rn(v0.z); h[3] = __int2half_rn(v0.w);
        h[4] = __int2half_rn(v1.x); h[5] = __int2half_rn(v1.y);
        h[6] = __int2half_rn(v1.z); h[7] = __int2half_rn(v1.w);
        *reinterpret_cast<uint4*>(g_wf16 + i) = *reinterpret_cast<const uint4*>(h);
    } else {
        const size_t j = i - WTOT;
        if (j >= XTOT) return;
        const float4 v0 = *reinterpret_cast<const float4*>(x + j);
        const float4 v1 = *reinterpret_cast<const float4*>(x + j + 4);
        __half h[8];
        h[0] = __float2half_rn(v0.x); h[1] = __float2half_rn(v0.y);
        h[2] = __float2half_rn(v0.z); h[3] = __float2half_rn(v0.w);
        h[4] = __float2half_rn(v1.x); h[5] = __float2half_rn(v1.y);
        h[6] = __float2half_rn(v1.z); h[7] = __float2half_rn(v1.w);
        *reinterpret_cast<uint4*>(g_xf16 + j) = *reinterpret_cast<const uint4*>(h);
    }
}

// ---------------- main GEMM ----------------
__global__ void __launch_bounds__(256, 2) w8_gemm_kernel(
    const float* __restrict__ scale,
    const float* __restrict__ bias,
    float* __restrict__ out)
{
    extern __shared__ __align__(128) char smem_raw[];
    const uint32_t base  = smem_to_u32(smem_raw);
    const uint32_t tiles = base + 128;
    // barriers: full[s] = base + 8*s ; empty[s] = base + 24 + 8*s

    const int tid  = threadIdx.x;
    const int lane = tid & 31;
    const int wid  = tid >> 5;
    const int warp_m = wid & 3;         // 4 row groups of 32
    const int warp_n = wid >> 2;        // 2 col groups of 64

    const int m0 = blockIdx.x * BM;
    const int n0 = blockIdx.y * BN;

    if (tid == 0) {
#pragma unroll
        for (int s = 0; s < STAGES; s++) {
            MBARRIER_INIT(base + 8 * s, 256);       // full
            MBARRIER_INIT(base + 24 + 8 * s, 8);    // empty: one arrive per warp
        }
    }
    __syncthreads();

    // cp.async coords
    const int base_r = tid >> 3;
    const int ch     = tid & 7;
    const uint32_t sOff0 = (uint32_t)(base_r * ROW_PITCH + ch * 16);
    const __half* gA0 = g_xf16 + (size_t)(m0 + base_r) * IN_F + ch * 8;
    const __half* gB0 = g_wf16 + (size_t)(n0 + base_r) * IN_F + ch * 8;

    // ldmatrix lane addresses
    const uint32_t a_lm = (uint32_t)((warp_m * 32 + (lane & 15)) * ROW_PITCH + (lane >> 4) * 16);
    const uint32_t b_lm = (uint32_t)((warp_n * 64 + (lane & 7) + ((lane >> 4) << 3)) * ROW_PITCH
                                     + ((lane >> 3) & 1) * 16);

    float acc[2][8][4];
#pragma unroll
    for (int mi = 0; mi < 2; mi++)
#pragma unroll
        for (int ni = 0; ni < 8; ni++)
#pragma unroll
            for (int j = 0; j < 4; j++) acc[mi][ni][j] = 0.f;

    // ---- prologue: produce stages 0,1 ----
#pragma unroll
    for (int s = 0; s < STAGES - 1; s++) {
        MBARRIER_WAIT_PARITY(base + 24 + 8 * s, 1);
        const uint32_t as = tiles + s * STAGE_BYTES;
        const uint32_t bs = as + A_STAGE;
        const int k0 = s * BK;
#pragma unroll
        for (int j = 0; j < 4; j++) {
            CP_ASYNC16(as + sOff0 + j * 32 * ROW_PITCH, gA0 + (size_t)j * 32 * IN_F + k0);
            CP_ASYNC16(bs + sOff0 + j * 32 * ROW_PITCH, gB0 + (size_t)j * 32 * IN_F + k0);
        }
        CP_ASYNC_ARRIVE_NOINC(base + 8 * s);
    }

    int pstage = STAGES - 1, pphase = 1;   // producer cursor
    int cstage = 0,          cphase = 0;   // consumer cursor

    for (int it = 0; it < NIT; ++it) {
        // ---- consume stage cstage FIRST ----
        MBARRIER_WAIT_PARITY(base + 8 * cstage, cphase);
        const uint32_t as = tiles + cstage * STAGE_BYTES;
        const uint32_t bs = as + A_STAGE;
#pragma unroll
        for (int ks = 0; ks < 4; ks++) {
            uint32_t a[2][4];
#pragma unroll
            for (int mi = 0; mi < 2; mi++)
                LDSM_X4(a[mi][0], a[mi][1], a[mi][2], a[mi][3],
                        as + a_lm + mi * 16 * ROW_PITCH + ks * 32);
            uint32_t b[4][4];
#pragma unroll
            for (int nt = 0; nt < 4; nt++)
                LDSM_X4(b[nt][0], b[nt][1], b[nt][2], b[nt][3],
                        bs + b_lm + nt * 16 * ROW_PITCH + ks * 32);
#pragma unroll
            for (int mi = 0; mi < 2; mi++)
#pragma unroll
                for (int ni = 0; ni < 8; ni++)
                    MMA16816(acc[mi][ni][0], acc[mi][ni][1], acc[mi][ni][2], acc[mi][ni][3],
                             a[mi][0], a[mi][1], a[mi][2], a[mi][3],
                             b[ni >> 1][(ni & 1) * 2], b[ni >> 1][(ni & 1) * 2 + 1]);
        }
        if (lane == 0) MBARRIER_ARRIVE(base + 24 + 8 * cstage);
        if (++cstage == STAGES) { cstage = 0; cphase ^= 1; }

        // ---- THEN produce stage for iteration it+STAGES-1 ----
        // (our MMAs for `it` are already in the tensor pipe; any straggler wait
        //  here overlaps tensor drain instead of preceding MMA issue)
        if (it + STAGES - 1 < NIT) {
            MBARRIER_WAIT_PARITY(base + 24 + 8 * pstage, pphase);
            const uint32_t pa = tiles + pstage * STAGE_BYTES;
            const uint32_t pb = pa + A_STAGE;
            const int k0 = (it + STAGES - 1) * BK;
#pragma unroll
            for (int j = 0; j < 4; j++) {
                CP_ASYNC16(pa + sOff0 + j * 32 * ROW_PITCH, gA0 + (size_t)j * 32 * IN_F + k0);
                CP_ASYNC16(pb + sOff0 + j * 32 * ROW_PITCH, gB0 + (size_t)j * 32 * IN_F + k0);
            }
            CP_ASYNC_ARRIVE_NOINC(base + 8 * pstage);
            if (++pstage == STAGES) { pstage = 0; pphase ^= 1; }
        }
    }

    // ---- epilogue: y = round_fp16(acc*scale + bias) as float32 ----
    const int qr = lane >> 2;
    const int qc = (lane & 3) * 2;
#pragma unroll
    for (int mi = 0; mi < 2; mi++) {
#pragma unroll
        for (int half_m = 0; half_m < 2; half_m++) {
            const int m = m0 + warp_m * 32 + mi * 16 + half_m * 8 + qr;
            float* orow = out + (size_t)m * OUT_F;
#pragma unroll
            for (int ni = 0; ni < 8; ni++) {
                const int n = n0 + warp_n * 64 + ni * 8 + qc;
                const float2 s2 = *reinterpret_cast<const float2*>(scale + n);
                const float2 b2 = *reinterpret_cast<const float2*>(bias + n);
                float y0 = acc[mi][ni][half_m * 2 + 0] * s2.x + b2.x;
                float y1 = acc[mi][ni][half_m * 2 + 1] * s2.y + b2.y;
                y0 = __half2float(__float2half_rn(y0));
                y1 = __half2float(__float2half_rn(y1));
                *reinterpret_cast<float2*>(orow + n) = make_float2(y0, y1);
            }
        }
    }
}

// ---------------- launch ----------------
extern "C" void kernel_launch(void* const* d_in, const int* in_sizes, int n_in,
                              void* d_out, int out_size) {
    const float* x     = (const float*)d_in[0];
    const int*   qw    = (const int*)d_in[1];
    const float* scale = (const float*)d_in[2];
    const float* bias  = (const float*)d_in[3];
    float*       out   = (float*)d_out;

    const size_t tot8 = (WTOT + XTOT) / 8;
    convert_all_kernel<<<(int)((tot8 + 255) / 256), 256>>>(qw, x);

    cudaFuncSetAttribute(w8_gemm_kernel, cudaFuncAttributeMaxDynamicSharedMemorySize, SMEM_TOTAL);
    dim3 grid(GRID_M, GRID_N);
    w8_gemm_kernel<<<grid, 256, SMEM_TOTAL>>>(scale, bias, out);
}